// round 10
// baseline (speedup 1.0000x reference)
#include <cuda_runtime.h>

// SoftBoundDDM_RT: 4096 trials x 2000-step leaky-DDM recurrence + soft bounds.
// One WARP per trial, 16 rounds of 128 contiguous elements; no __syncthreads,
// no shared memory. Depth-2 software prefetch (rounds r+1, r+2 in flight while
// consuming r); sigmoids via tanh.approx.f32.
// Linear recurrence solved as a weighted prefix SUM:
//   e[T] = D^T * ( e0 + sum_{i<T} u[i] * D^-(i+1) ),  D = 0.99999.

constexpr int   N_T    = 2000;
constexpr int   TPB    = 128;         // 4 warps = 4 trials per block
constexpr int   WPB    = TPB / 32;
constexpr int   ROUNDS = 16;          // 15 full 128-elem rounds + 80-elem tail
constexpr float DT     = 0.001f;
constexpr float LEAK   = 0.01f;
constexpr float TC     = 0.01f;       // TIME_CONSTANT
constexpr float DECAY  = 1.0f - LEAK * DT;             // 0.99999
constexpr float DINV   = 1.0f / DECAY;
constexpr float LN_D   = -1.0000050000333e-5f;         // ln(0.99999)
constexpr float SQVDT  = 0.03162277660168379332f;      // sqrt(VARIANCE*DT)
constexpr float D128   = 0.99872081245862f;            // DECAY^128
constexpr float DI128  = 1.00128082595776f;            // DECAY^-128

// D^k for k=0..3 (immediates)
constexpr float DP1 = 0.99999f;
constexpr float DP2 = 0.9999800001f;
constexpr float DP3 = 0.9999700003f;

__device__ __forceinline__ float tanh_fast(float x) {
    float y;
    asm("tanh.approx.f32 %0, %1;" : "=f"(y) : "f"(x));
    return y;
}

__global__ __launch_bounds__(TPB, 7)
void ddm_kernel(const float* __restrict__ stim,
                const float* __restrict__ noise,
                const float* __restrict__ pa,
                const float* __restrict__ pz,
                const float* __restrict__ pg,
                const float* __restrict__ po,
                const float* __restrict__ pb,
                float* __restrict__ out,
                long long total_elems,      // n_trials * N_T
                int n_trials)
{
    const int lane  = threadIdx.x & 31;
    const int warp  = threadIdx.x >> 5;
    const int trial = blockIdx.x * WPB + warp;
    if (trial >= n_trials) return;

    const float a    = __ldg(pa);
    const float z    = __ldg(pz);
    const float g    = __ldg(pg);
    const float off  = __ldg(po);
    const float beta = __ldg(pb);

    const float e0     = z * a;
    const float cstim  = g * DT;
    const float cconst = off * DT + LEAK * e0 * DT;
    const float hb     = 0.5f * beta;         // sigmoid(x)=0.5+0.5*tanh(x/2)
    const float hba    = hb * a;

    // per-lane decay powers at pos0 = lane*4:  Gd = D^pos, F = D^-pos
    const int   pos0 = lane * 4;
    float Gd = __expf(LN_D * (float)pos0);
    float F  = __expf(-LN_D * (float)pos0);

    const size_t tb = (size_t)trial * N_T;
    const float* sp = stim  + tb;
    const float* np = noise + tb;
    float* dvout = out + tb;
    float* h1out = out + (size_t)total_elems + tb;
    float* h0out = out + 2 * (size_t)total_elems + tb;

    float eR = e0;                    // e0 + weighted sum of all prior rounds

    const bool tailLive = (lane < 20);    // last round covers 80 elems

    // ---- prologue: prefetch rounds 0 and 1 (depth-2 pipeline) ----
    float4 sB0, nB0, sB1, nB1;
    sB0 = __ldcs(reinterpret_cast<const float4*>(sp + pos0));
    nB0 = __ldcs(reinterpret_cast<const float4*>(np + pos0));
    sB1 = __ldcs(reinterpret_cast<const float4*>(sp + 128 + pos0));
    nB1 = __ldcs(reinterpret_cast<const float4*>(np + 128 + pos0));

    #pragma unroll
    for (int r = 0; r < ROUNDS; r++) {
        const int  pos  = r * 128 + pos0;
        const bool live = (r < ROUNDS - 1) || tailLive;

        // consume round r's buffer into u immediately (frees the slot)
        const float4 s4 = (r & 1) ? sB1 : sB0;
        const float4 n4 = (r & 1) ? nB1 : nB0;

        const float u0 = fmaf(cstim, s4.x, fmaf(SQVDT, n4.x, cconst));
        const float u1 = fmaf(cstim, s4.y, fmaf(SQVDT, n4.y, cconst));
        const float u2 = fmaf(cstim, s4.z, fmaf(SQVDT, n4.z, cconst));
        const float u3 = fmaf(cstim, s4.w, fmaf(SQVDT, n4.w, cconst));

        // ---- issue round r+2 loads into the freed slot ----
        if (r + 2 < ROUNDS) {
            const bool liveP = (r + 2 < ROUNDS - 1) || tailLive;
            if (liveP) {
                const float4 sN = __ldcs(reinterpret_cast<const float4*>(sp + pos + 256));
                const float4 nN = __ldcs(reinterpret_cast<const float4*>(np + pos + 256));
                if (r & 1) { sB1 = sN; nB1 = nN; } else { sB0 = sN; nB0 = nN; }
            }
        }

        // local weighted prefix q_k = sum_{j<=k} u_j * DINV^(j+1)
        const float q0 = u0 * DINV;
        const float q1 = fmaf(u1, DINV * DINV, q0);
        const float q2 = fmaf(u2, DINV * DINV * DINV, q1);
        const float q3 = fmaf(u3, DINV * DINV * DINV * DINV, q2);

        const float c = live ? F * q3 : 0.0f;   // lane chunk total (global wt)

        // inclusive warp add-scan (independent of carry eR)
        float si = c;
        #pragma unroll
        for (int d = 1; d < 32; d <<= 1) {
            const float o = __shfl_up_sync(0xffffffffu, si, d);
            if (lane >= d) si += o;
        }
        const float ex  = si - c;                          // exclusive prefix
        const float tot = __shfl_sync(0xffffffffu, si, 31);

        const float basev = eR + ex;   // e0 + full weighted prefix before pos

        // evidence / dv / sigmoids for the 4 elements
        const float i0 = basev;
        const float i1 = fmaf(F, q0, basev);
        const float i2 = fmaf(F, q1, basev);
        const float i3 = fmaf(F, q2, basev);

        const float ev0 = Gd * i0;
        const float ev1 = Gd * (DP1 * i1);
        const float ev2 = Gd * (DP2 * i2);
        const float ev3 = Gd * (DP3 * i3);

        const float fp  = (float)pos;
        const float dv0 = fmaf(fp * TC,          ev0 - e0, e0);
        const float dv1 = fmaf((fp + 1.f) * TC,  ev1 - e0, e0);
        const float dv2 = fmaf((fp + 2.f) * TC,  ev2 - e0, e0);
        const float dv3 = fmaf((fp + 3.f) * TC,  ev3 - e0, e0);

        if (live) {
            __stcs(reinterpret_cast<float4*>(dvout + pos),
                   make_float4(dv0, dv1, dv2, dv3));
            // h1 = 0.5 + 0.5*tanh(hb*dv - hba)
            const float t10 = tanh_fast(fmaf(hb, dv0, -hba));
            const float t11 = tanh_fast(fmaf(hb, dv1, -hba));
            const float t12 = tanh_fast(fmaf(hb, dv2, -hba));
            const float t13 = tanh_fast(fmaf(hb, dv3, -hba));
            __stcs(reinterpret_cast<float4*>(h1out + pos),
                   make_float4(fmaf(0.5f, t10, 0.5f), fmaf(0.5f, t11, 0.5f),
                               fmaf(0.5f, t12, 0.5f), fmaf(0.5f, t13, 0.5f)));
            // h0 = 0.5 - 0.5*tanh(hb*dv)
            const float t00 = tanh_fast(hb * dv0);
            const float t01 = tanh_fast(hb * dv1);
            const float t02 = tanh_fast(hb * dv2);
            const float t03 = tanh_fast(hb * dv3);
            __stcs(reinterpret_cast<float4*>(h0out + pos),
                   make_float4(fmaf(-0.5f, t00, 0.5f), fmaf(-0.5f, t01, 0.5f),
                               fmaf(-0.5f, t02, 0.5f), fmaf(-0.5f, t03, 0.5f)));
        }

        eR += tot;                    // the ONLY cross-round dependency
        F  *= DI128;                  // advance lane decay powers by 128 steps
        Gd *= D128;
    }
}

extern "C" void kernel_launch(void* const* d_in, const int* in_sizes, int n_in,
                              void* d_out, int out_size)
{
    const float* stim  = (const float*)d_in[0];
    const float* noise = (const float*)d_in[1];
    const float* pa    = (const float*)d_in[2];
    const float* pz    = (const float*)d_in[3];
    const float* pg    = (const float*)d_in[4];
    const float* po    = (const float*)d_in[5];
    const float* pb    = (const float*)d_in[6];
    float* out = (float*)d_out;

    const long long total = in_sizes[0];          // n_trials * N_T
    const int n_trials = (int)(total / N_T);
    const int n_blocks = (n_trials + WPB - 1) / WPB;   // 1024

    ddm_kernel<<<n_blocks, TPB>>>(stim, noise, pa, pz, pg, po, pb, out, total, n_trials);
}

// round 14
// speedup vs baseline: 1.0790x; 1.0790x over previous
#include <cuda_runtime.h>

// SoftBoundDDM_RT: 4096 trials x 2000-step leaky-DDM recurrence + soft bounds.
// TWO warps per trial (8192 warps total): warp A outputs [0,1000), warp B runs
// a reduce-only pass over [0,1000) (order-independent weighted sum => no scan,
// one butterfly) then outputs [1000,2000). No smem, no __syncthreads.
// Linear recurrence solved as a weighted prefix SUM:
//   e[T] = D^T * ( e0 + sum_{i<T} u[i] * D^-(i+1) ),  D = 0.99999.

constexpr int   N_T    = 2000;
constexpr int   HALF   = 1000;
constexpr int   TPB    = 128;         // 4 warps = 2 trials per block
constexpr int   RND    = 8;           // rounds per half: 7 full + 104-elem tail
constexpr float DT     = 0.001f;
constexpr float LEAK   = 0.01f;
constexpr float TC     = 0.01f;       // TIME_CONSTANT
constexpr float DECAY  = 1.0f - LEAK * DT;             // 0.99999
constexpr float DINV   = 1.0f / DECAY;
constexpr float LN_D   = -1.0000050000333e-5f;         // ln(0.99999)
constexpr float SQVDT  = 0.03162277660168379332f;      // sqrt(VARIANCE*DT)
constexpr float D128   = 0.99872081245862f;            // DECAY^128
constexpr float DI128  = 1.00128082595776f;            // DECAY^-128

// D^k for k=0..3 (immediates)
constexpr float DP1 = 0.99999f;
constexpr float DP2 = 0.9999800001f;
constexpr float DP3 = 0.9999700003f;

__device__ __forceinline__ float tanh_fast(float x) {
    float y;
    asm("tanh.approx.f32 %0, %1;" : "=f"(y) : "f"(x));
    return y;
}

__global__ __launch_bounds__(TPB, 8)
void ddm_kernel(const float* __restrict__ stim,
                const float* __restrict__ noise,
                const float* __restrict__ pa,
                const float* __restrict__ pz,
                const float* __restrict__ pg,
                const float* __restrict__ po,
                const float* __restrict__ pb,
                float* __restrict__ out,
                long long total_elems,      // n_trials * N_T
                int n_trials)
{
    const int lane  = threadIdx.x & 31;
    const int warp  = threadIdx.x >> 5;
    const int half  = warp & 1;                    // 0: front half, 1: back half
    const int trial = blockIdx.x * 2 + (warp >> 1);
    if (trial >= n_trials) return;

    const float a    = __ldg(pa);
    const float z    = __ldg(pz);
    const float g    = __ldg(pg);
    const float off  = __ldg(po);
    const float beta = __ldg(pb);

    const float e0     = z * a;
    const float cstim  = g * DT;
    const float cconst = off * DT + LEAK * e0 * DT;
    const float hb     = 0.5f * beta;         // sigmoid(x)=0.5+0.5*tanh(x/2)
    const float hba    = hb * a;

    const size_t tb = (size_t)trial * N_T;
    const float* sp = stim  + tb;
    const float* np = noise + tb;
    float* dvout = out + tb;
    float* h1out = out + (size_t)total_elems + tb;
    float* h0out = out + 2 * (size_t)total_elems + tb;

    const bool tailLive = (lane < 26);        // last round of a half: 104 elems

    float eR = e0;

    // ================= reduce-only prefix pass (back-half warps) ============
    if (half) {
        float Fr  = __expf(-LN_D * (float)(lane * 4));
        float acc = 0.0f;
        #pragma unroll
        for (int r = 0; r < RND; r++) {
            const int  pos  = r * 128 + lane * 4;
            const bool live = (r < RND - 1) || tailLive;
            float4 s4 = make_float4(0.f, 0.f, 0.f, 0.f);
            float4 n4 = make_float4(0.f, 0.f, 0.f, 0.f);
            if (live) {
                s4 = *reinterpret_cast<const float4*>(sp + pos);
                n4 = *reinterpret_cast<const float4*>(np + pos);
            }
            const float u0 = fmaf(cstim, s4.x, fmaf(SQVDT, n4.x, cconst));
            const float u1 = fmaf(cstim, s4.y, fmaf(SQVDT, n4.y, cconst));
            const float u2 = fmaf(cstim, s4.z, fmaf(SQVDT, n4.z, cconst));
            const float u3 = fmaf(cstim, s4.w, fmaf(SQVDT, n4.w, cconst));
            float loc = u0 * DINV;
            loc = fmaf(u1, DINV * DINV, loc);
            loc = fmaf(u2, DINV * DINV * DINV, loc);
            loc = fmaf(u3, DINV * DINV * DINV * DINV, loc);
            if (live) acc = fmaf(Fr, loc, acc);
            Fr *= DI128;
        }
        // butterfly reduce (order-independent weighted sum)
        #pragma unroll
        for (int d = 16; d >= 1; d >>= 1)
            acc += __shfl_xor_sync(0xffffffffu, acc, d);
        eR += acc;                     // e0 + weighted sum of elements [0,1000)
    }

    // ======================= output pass over this half =====================
    const int   hb0  = half * HALF;
    const int   pos0 = hb0 + lane * 4;
    float Gd = __expf(LN_D * (float)pos0);
    float F  = __expf(-LN_D * (float)pos0);

    // depth-1 prefetch
    float4 sA = *reinterpret_cast<const float4*>(sp + pos0);
    float4 nA = *reinterpret_cast<const float4*>(np + pos0);

    #pragma unroll
    for (int r = 0; r < RND; r++) {
        const int  pos  = hb0 + r * 128 + lane * 4;
        const bool live = (r < RND - 1) || tailLive;

        // prefetch next round before consuming this one
        float4 sB = make_float4(0.f, 0.f, 0.f, 0.f);
        float4 nB = make_float4(0.f, 0.f, 0.f, 0.f);
        if (r + 1 < RND) {
            const bool liveN = (r + 1 < RND - 1) || tailLive;
            if (liveN) {
                sB = __ldcs(reinterpret_cast<const float4*>(sp + pos + 128));
                nB = __ldcs(reinterpret_cast<const float4*>(np + pos + 128));
            }
        }

        // u and local weighted prefix q_k = sum_{j<=k} u_j * DINV^(j+1)
        const float u0 = fmaf(cstim, sA.x, fmaf(SQVDT, nA.x, cconst));
        const float u1 = fmaf(cstim, sA.y, fmaf(SQVDT, nA.y, cconst));
        const float u2 = fmaf(cstim, sA.z, fmaf(SQVDT, nA.z, cconst));
        const float u3 = fmaf(cstim, sA.w, fmaf(SQVDT, nA.w, cconst));
        const float q0 = u0 * DINV;
        const float q1 = fmaf(u1, DINV * DINV, q0);
        const float q2 = fmaf(u2, DINV * DINV * DINV, q1);
        const float q3 = fmaf(u3, DINV * DINV * DINV * DINV, q2);

        const float c = live ? F * q3 : 0.0f;   // lane chunk total (global wt)

        // inclusive warp add-scan (independent of carry eR)
        float si = c;
        #pragma unroll
        for (int d = 1; d < 32; d <<= 1) {
            const float o = __shfl_up_sync(0xffffffffu, si, d);
            if (lane >= d) si += o;
        }
        const float ex  = si - c;                          // exclusive prefix
        const float tot = __shfl_sync(0xffffffffu, si, 31);

        const float basev = eR + ex;   // e0 + full weighted prefix before pos

        // evidence / dv / sigmoids for the 4 elements
        const float i0 = basev;
        const float i1 = fmaf(F, q0, basev);
        const float i2 = fmaf(F, q1, basev);
        const float i3 = fmaf(F, q2, basev);

        const float ev0 = Gd * i0;
        const float ev1 = Gd * (DP1 * i1);
        const float ev2 = Gd * (DP2 * i2);
        const float ev3 = Gd * (DP3 * i3);

        const float fp  = (float)pos;
        const float dv0 = fmaf(fp * TC,          ev0 - e0, e0);
        const float dv1 = fmaf((fp + 1.f) * TC,  ev1 - e0, e0);
        const float dv2 = fmaf((fp + 2.f) * TC,  ev2 - e0, e0);
        const float dv3 = fmaf((fp + 3.f) * TC,  ev3 - e0, e0);

        if (live) {
            __stcs(reinterpret_cast<float4*>(dvout + pos),
                   make_float4(dv0, dv1, dv2, dv3));
            // h1 = 0.5 + 0.5*tanh(hb*dv - hba)
            const float t10 = tanh_fast(fmaf(hb, dv0, -hba));
            const float t11 = tanh_fast(fmaf(hb, dv1, -hba));
            const float t12 = tanh_fast(fmaf(hb, dv2, -hba));
            const float t13 = tanh_fast(fmaf(hb, dv3, -hba));
            __stcs(reinterpret_cast<float4*>(h1out + pos),
                   make_float4(fmaf(0.5f, t10, 0.5f), fmaf(0.5f, t11, 0.5f),
                               fmaf(0.5f, t12, 0.5f), fmaf(0.5f, t13, 0.5f)));
            // h0 = 0.5 - 0.5*tanh(hb*dv)
            const float t00 = tanh_fast(hb * dv0);
            const float t01 = tanh_fast(hb * dv1);
            const float t02 = tanh_fast(hb * dv2);
            const float t03 = tanh_fast(hb * dv3);
            __stcs(reinterpret_cast<float4*>(h0out + pos),
                   make_float4(fmaf(-0.5f, t00, 0.5f), fmaf(-0.5f, t01, 0.5f),
                               fmaf(-0.5f, t02, 0.5f), fmaf(-0.5f, t03, 0.5f)));
        }

        eR += tot;                    // the ONLY cross-round dependency
        F  *= DI128;                  // advance lane decay powers by 128 steps
        Gd *= D128;

        sA = sB;                      // rotate prefetch buffer
        nA = nB;
    }
}

extern "C" void kernel_launch(void* const* d_in, const int* in_sizes, int n_in,
                              void* d_out, int out_size)
{
    const float* stim  = (const float*)d_in[0];
    const float* noise = (const float*)d_in[1];
    const float* pa    = (const float*)d_in[2];
    const float* pz    = (const float*)d_in[3];
    const float* pg    = (const float*)d_in[4];
    const float* po    = (const float*)d_in[5];
    const float* pb    = (const float*)d_in[6];
    float* out = (float*)d_out;

    const long long total = in_sizes[0];          // n_trials * N_T
    const int n_trials = (int)(total / N_T);
    const int n_blocks = (n_trials + 1) / 2;      // 2 trials per block

    ddm_kernel<<<n_blocks, TPB>>>(stim, noise, pa, pz, pg, po, pb, out, total, n_trials);
}

// round 15
// speedup vs baseline: 1.1070x; 1.0259x over previous
#include <cuda_runtime.h>

// SoftBoundDDM_RT: 4096 trials x 2000-step leaky-DDM recurrence + soft bounds.
// TWO warps per trial, BALANCED split at 1280:
//   warp A: outputs [0,1280)                        (~25600 traffic units)
//   warp B: reduce-only [0,1280) + outputs [1280,2000)  (~24640 units)
// Reduce is an order-independent weighted sum (no scan, one butterfly).
// No smem, no __syncthreads. Linear recurrence as weighted prefix SUM:
//   e[T] = D^T * ( e0 + sum_{i<T} u[i] * D^-(i+1) ),  D = 0.99999.

constexpr int   N_T    = 2000;
constexpr int   SPLIT  = 1280;        // warp A outputs [0,SPLIT)
constexpr int   RND_A  = 10;          // 10 full 128-rounds
constexpr int   RND_R  = 10;          // reduce rounds (full)
constexpr int   RND_B  = 6;           // 5 full + 80-elem tail (720 total)
constexpr int   TPB    = 128;         // 4 warps = 2 trials per block
constexpr float DT     = 0.001f;
constexpr float LEAK   = 0.01f;
constexpr float TC     = 0.01f;       // TIME_CONSTANT
constexpr float DECAY  = 1.0f - LEAK * DT;             // 0.99999
constexpr float DINV   = 1.0f / DECAY;
constexpr float LN_D   = -1.0000050000333e-5f;         // ln(0.99999)
constexpr float SQVDT  = 0.03162277660168379332f;      // sqrt(VARIANCE*DT)
constexpr float D128   = 0.99872081245862f;            // DECAY^128
constexpr float DI128  = 1.00128082595776f;            // DECAY^-128

// D^k for k=0..3 (immediates)
constexpr float DP1 = 0.99999f;
constexpr float DP2 = 0.9999800001f;
constexpr float DP3 = 0.9999700003f;

__device__ __forceinline__ float tanh_fast(float x) {
    float y;
    asm("tanh.approx.f32 %0, %1;" : "=f"(y) : "f"(x));
    return y;
}

__global__ __launch_bounds__(TPB, 8)
void ddm_kernel(const float* __restrict__ stim,
                const float* __restrict__ noise,
                const float* __restrict__ pa,
                const float* __restrict__ pz,
                const float* __restrict__ pg,
                const float* __restrict__ po,
                const float* __restrict__ pb,
                float* __restrict__ out,
                long long total_elems,      // n_trials * N_T
                int n_trials)
{
    const int lane  = threadIdx.x & 31;
    const int warp  = threadIdx.x >> 5;
    const int half  = warp & 1;                    // 0: warp A, 1: warp B
    const int trial = blockIdx.x * 2 + (warp >> 1);
    if (trial >= n_trials) return;

    const float a    = __ldg(pa);
    const float z    = __ldg(pz);
    const float g    = __ldg(pg);
    const float off  = __ldg(po);
    const float beta = __ldg(pb);

    const float e0     = z * a;
    const float cstim  = g * DT;
    const float cconst = off * DT + LEAK * e0 * DT;
    const float hb     = 0.5f * beta;         // sigmoid(x)=0.5+0.5*tanh(x/2)
    const float hba    = hb * a;

    const size_t tb = (size_t)trial * N_T;
    const float* sp = stim  + tb;
    const float* np = noise + tb;
    float* dvout = out + tb;
    float* h1out = out + (size_t)total_elems + tb;
    float* h0out = out + 2 * (size_t)total_elems + tb;

    // one output round: computes & stores 4 elems at pos, returns warp total
    auto out_round = [&](int pos, bool live, float F, float Gd, float eR,
                         const float4& s4, const float4& n4) -> float {
        const float u0 = fmaf(cstim, s4.x, fmaf(SQVDT, n4.x, cconst));
        const float u1 = fmaf(cstim, s4.y, fmaf(SQVDT, n4.y, cconst));
        const float u2 = fmaf(cstim, s4.z, fmaf(SQVDT, n4.z, cconst));
        const float u3 = fmaf(cstim, s4.w, fmaf(SQVDT, n4.w, cconst));
        const float q0 = u0 * DINV;
        const float q1 = fmaf(u1, DINV * DINV, q0);
        const float q2 = fmaf(u2, DINV * DINV * DINV, q1);
        const float q3 = fmaf(u3, DINV * DINV * DINV * DINV, q2);

        const float c = live ? F * q3 : 0.0f;

        float si = c;
        #pragma unroll
        for (int d = 1; d < 32; d <<= 1) {
            const float o = __shfl_up_sync(0xffffffffu, si, d);
            if (lane >= d) si += o;
        }
        const float ex  = si - c;
        const float tot = __shfl_sync(0xffffffffu, si, 31);

        const float basev = eR + ex;

        const float i0 = basev;
        const float i1 = fmaf(F, q0, basev);
        const float i2 = fmaf(F, q1, basev);
        const float i3 = fmaf(F, q2, basev);

        const float ev0 = Gd * i0;
        const float ev1 = Gd * (DP1 * i1);
        const float ev2 = Gd * (DP2 * i2);
        const float ev3 = Gd * (DP3 * i3);

        const float fp  = (float)pos;
        const float dv0 = fmaf(fp * TC,          ev0 - e0, e0);
        const float dv1 = fmaf((fp + 1.f) * TC,  ev1 - e0, e0);
        const float dv2 = fmaf((fp + 2.f) * TC,  ev2 - e0, e0);
        const float dv3 = fmaf((fp + 3.f) * TC,  ev3 - e0, e0);

        if (live) {
            __stcs(reinterpret_cast<float4*>(dvout + pos),
                   make_float4(dv0, dv1, dv2, dv3));
            const float t10 = tanh_fast(fmaf(hb, dv0, -hba));
            const float t11 = tanh_fast(fmaf(hb, dv1, -hba));
            const float t12 = tanh_fast(fmaf(hb, dv2, -hba));
            const float t13 = tanh_fast(fmaf(hb, dv3, -hba));
            __stcs(reinterpret_cast<float4*>(h1out + pos),
                   make_float4(fmaf(0.5f, t10, 0.5f), fmaf(0.5f, t11, 0.5f),
                               fmaf(0.5f, t12, 0.5f), fmaf(0.5f, t13, 0.5f)));
            const float t00 = tanh_fast(hb * dv0);
            const float t01 = tanh_fast(hb * dv1);
            const float t02 = tanh_fast(hb * dv2);
            const float t03 = tanh_fast(hb * dv3);
            __stcs(reinterpret_cast<float4*>(h0out + pos),
                   make_float4(fmaf(-0.5f, t00, 0.5f), fmaf(-0.5f, t01, 0.5f),
                               fmaf(-0.5f, t02, 0.5f), fmaf(-0.5f, t03, 0.5f)));
        }
        return tot;
    };

    if (half == 0) {
        // ================= warp A: output [0,1280), all rounds full =========
        const int pos0 = lane * 4;
        float Gd = __expf(LN_D * (float)pos0);
        float F  = __expf(-LN_D * (float)pos0);
        float eR = e0;

        // depth-1 prefetch (default cache: warp B re-reads this region)
        float4 sA = *reinterpret_cast<const float4*>(sp + pos0);
        float4 nA = *reinterpret_cast<const float4*>(np + pos0);

        #pragma unroll
        for (int r = 0; r < RND_A; r++) {
            const int pos = r * 128 + pos0;
            float4 sB, nB;
            if (r + 1 < RND_A) {
                sB = *reinterpret_cast<const float4*>(sp + pos + 128);
                nB = *reinterpret_cast<const float4*>(np + pos + 128);
            }
            eR += out_round(pos, true, F, Gd, eR, sA, nA);
            F  *= DI128;
            Gd *= D128;
            if (r + 1 < RND_A) { sA = sB; nA = nB; }
        }
    } else {
        // ====== warp B: reduce [0,1280) (no scan, no tail), then output =====
        float Fr  = __expf(-LN_D * (float)(lane * 4));
        float acc = 0.0f;
        #pragma unroll
        for (int r = 0; r < RND_R; r++) {
            const int pos = r * 128 + lane * 4;
            const float4 s4 = *reinterpret_cast<const float4*>(sp + pos);
            const float4 n4 = *reinterpret_cast<const float4*>(np + pos);
            const float u0 = fmaf(cstim, s4.x, fmaf(SQVDT, n4.x, cconst));
            const float u1 = fmaf(cstim, s4.y, fmaf(SQVDT, n4.y, cconst));
            const float u2 = fmaf(cstim, s4.z, fmaf(SQVDT, n4.z, cconst));
            const float u3 = fmaf(cstim, s4.w, fmaf(SQVDT, n4.w, cconst));
            float loc = u0 * DINV;
            loc = fmaf(u1, DINV * DINV, loc);
            loc = fmaf(u2, DINV * DINV * DINV, loc);
            loc = fmaf(u3, DINV * DINV * DINV * DINV, loc);
            acc = fmaf(Fr, loc, acc);
            Fr *= DI128;
        }
        #pragma unroll
        for (int d = 16; d >= 1; d >>= 1)
            acc += __shfl_xor_sync(0xffffffffu, acc, d);
        float eR = e0 + acc;           // e0 + weighted sum of [0,1280)

        // ---- output [1280,2000): 5 full rounds + 80-elem tail --------------
        const int  pos0     = SPLIT + lane * 4;
        const bool tailLive = (lane < 20);
        float Gd = __expf(LN_D * (float)pos0);
        float F  = __expf(-LN_D * (float)pos0);

        float4 sA = __ldcs(reinterpret_cast<const float4*>(sp + pos0));
        float4 nA = __ldcs(reinterpret_cast<const float4*>(np + pos0));

        #pragma unroll
        for (int r = 0; r < RND_B; r++) {
            const int  pos  = SPLIT + r * 128 + lane * 4;
            const bool live = (r < RND_B - 1) || tailLive;
            float4 sB = make_float4(0.f, 0.f, 0.f, 0.f);
            float4 nB = make_float4(0.f, 0.f, 0.f, 0.f);
            if (r + 1 < RND_B) {
                const bool liveN = (r + 1 < RND_B - 1) || tailLive;
                if (liveN) {
                    sB = __ldcs(reinterpret_cast<const float4*>(sp + pos + 128));
                    nB = __ldcs(reinterpret_cast<const float4*>(np + pos + 128));
                }
            }
            eR += out_round(pos, live, F, Gd, eR, sA, nA);
            F  *= DI128;
            Gd *= D128;
            sA = sB;
            nA = nB;
        }
    }
}

extern "C" void kernel_launch(void* const* d_in, const int* in_sizes, int n_in,
                              void* d_out, int out_size)
{
    const float* stim  = (const float*)d_in[0];
    const float* noise = (const float*)d_in[1];
    const float* pa    = (const float*)d_in[2];
    const float* pz    = (const float*)d_in[3];
    const float* pg    = (const float*)d_in[4];
    const float* po    = (const float*)d_in[5];
    const float* pb    = (const float*)d_in[6];
    float* out = (float*)d_out;

    const long long total = in_sizes[0];          // n_trials * N_T
    const int n_trials = (int)(total / N_T);
    const int n_blocks = (n_trials + 1) / 2;      // 2 trials per block

    ddm_kernel<<<n_blocks, TPB>>>(stim, noise, pa, pz, pg, po, pb, out, total, n_trials);
}